// round 15
// baseline (speedup 1.0000x reference)
#include <cuda_runtime.h>
#include <math.h>

#define NBATCH 4
#define LTOK   4096
#define CDIM   256
#define NHEAD  8
#define NTOPIC 100
#define NSAMP  6
#define NBM    48

typedef unsigned long long ull;

// ======================= device scratch =======================
__device__ float g_f[2*NBATCH*LTOK*CDIM];
__device__ float g_fo[NBATCH*2*LTOK*CDIM];
__device__ float g_seeds[NBATCH*NTOPIC*CDIM];
__device__ float g_seedsF[NBATCH*NTOPIC*CDIM];
__device__ float g_nf[NBM*LTOK*CDIM];
__device__ float g_q[NBM*LTOK*CDIM];
__device__ float g_k[NBM*LTOK*CDIM];
__device__ float g_v[NBM*LTOK*CDIM];
__device__ float g_hid[NBM*LTOK*2*CDIM];
__device__ float g_ffn[NBM*LTOK*CDIM];
__device__ float g_KV[NBM*NHEAD*32*32];
__device__ float g_Ksum[NBM*NHEAD*32];
__device__ float g_dm[NBATCH*2*LTOK*NTOPIC];
__device__ float g_tm[NBATCH*NTOPIC*NTOPIC];
__device__ float g_cmax[NBATCH*NTOPIC];
__device__ float g_csum[NBATCH*NTOPIC];
__device__ float g_topic[NBATCH*NTOPIC*96];
__device__ float g_sumh[2*NBATCH*NTOPIC];
__device__ float g_cond[NSAMP];
__device__ int   g_amax[NBATCH*2*LTOK];
__device__ int   g_tmidx[NBATCH*NTOPIC];
__device__ int   g_inds[NBATCH*NSAMP];
__device__ int   g_sel[2*NSAMP*NBATCH*LTOK];
__device__ int   g_cnt[2*NSAMP*NBATCH];
__device__ int   g_cntm[NBM];

// ======================= generic =======================
__global__ void zero_k(float* p, long n){
    long i=(long)blockIdx.x*blockDim.x+threadIdx.x; if(i<n) p[i]=0.f;
}
__global__ void zero2_k(float* p1, long n1, float* p2, long n2){
    long i=(long)blockIdx.x*blockDim.x+threadIdx.x;
    if(i<n1) p1[i]=0.f;
    if(i<n2) p2[i]=0.f;
}
__global__ void copy_k(float* d, const float* s, long n){
    long i=(long)blockIdx.x*blockDim.x+threadIdx.x; if(i<n) d[i]=s[i];
}
__global__ void bcast_seeds_k(const float* st){
    long i=(long)blockIdx.x*blockDim.x+threadIdx.x;
    long tot=(long)NBATCH*NTOPIC*CDIM;
    if(i<tot) g_seeds[i]=st[i%(NTOPIC*CDIM)];
}
__global__ void concatfeat_k(const float* f0, const float* f1){
    long i=(long)blockIdx.x*blockDim.x+threadIdx.x;
    long tot=(long)NBATCH*2*LTOK*CDIM; if(i>=tot) return;
    int n=(int)(i/(2L*LTOK*CDIM));
    long rem=i-(long)n*2*LTOK*CDIM;
    int row=(int)(rem/CDIM); int c=(int)(rem-(long)row*CDIM);
    if(row<LTOK) g_fo[i]=f0[((long)n*LTOK+row)*CDIM+c];
    else         g_fo[i]=f1[((long)n*LTOK+row-LTOK)*CDIM+c];
}

// ======================= GEMM: 128x64, tf32 mma 3-product, cp.async pipeline =======================
struct GOp {
    const float* A; const float* A2; const float* B; float* C;
    int M,N,K,transB,ldB; long strideB; int rpb; const int* counts; float alpha; int epi;
};

// smem floats: A[2][128][36] @0 (9216), B[2][2304] @9216 ([k][72] or [n][36])
#define GEMM_SMEM ((2*128*36 + 2*2304)*4)   // 55296 B

__device__ __forceinline__ unsigned cvt_tf32(float x){
    unsigned t; asm("cvt.rna.tf32.f32 %0,%1;":"=r"(t):"f"(x)); return t;
}
__device__ __forceinline__ void cpa16(unsigned dst,const float* src,int sb){
    asm volatile("cp.async.cg.shared.global [%0],[%1],16,%2;"
                 ::"r"(dst),"l"(src),"r"(sb):"memory");
}
#define MMA8(c,a,b) asm volatile( \
    "mma.sync.aligned.m16n8k8.row.col.f32.tf32.tf32.f32 {%0,%1,%2,%3},{%4,%5,%6,%7},{%8,%9},{%0,%1,%2,%3};" \
    :"+f"(c[0]),"+f"(c[1]),"+f"(c[2]),"+f"(c[3]) \
    :"r"(a[0]),"r"(a[1]),"r"(a[2]),"r"(a[3]),"r"(b[0]),"r"(b[1]))

__global__ void __launch_bounds__(256,3) gemm_k(GOp o0, GOp o1, GOp o2)
{
    GOp o = (blockIdx.z==0)?o0:((blockIdx.z==1)?o1:o2);
    int bm=blockIdx.y*128, bn=blockIdx.x*64;
    if(bm>=o.M || bn>=o.N) return;
    if(o.counts){ int nb=bm/o.rpb; if(bm-nb*o.rpb>=o.counts[nb]) return; }
    const float* Bp = o.B + (o.strideB ? (long)(bm/o.rpb)*o.strideB : 0);
    int lda = o.A2 ? 256 : o.K;

    extern __shared__ float smf[];
    unsigned sbase;
    asm("{.reg .u64 t; cvta.to.shared.u64 t,%1; cvt.u32.u64 %0,t;}":"=r"(sbase):"l"(smf));
    unsigned sA=sbase, sB=sbase+36864;

    int tid=threadIdx.x;
    int wid=tid>>5, lid=tid&31;
    int g=lid>>2, tg=lid&3;
    int wm=(wid&3)*32, wn=(wid>>2)*32;

    float acc[2][4][4];
    #pragma unroll
    for(int mt=0;mt<2;mt++)
        #pragma unroll
        for(int nt=0;nt<4;nt++)
            #pragma unroll
            for(int e=0;e<4;e++) acc[mt][nt][e]=0.f;

    auto issue=[&](int slab,int db){
        int k0=slab*32;
        const float* Ap; int kof;
        if(o.A2 && k0>=256){ Ap=o.A2; kof=k0-256; } else { Ap=o.A; kof=k0; }
        #pragma unroll
        for(int i=0;i<4;i++){
            int t=tid*4+i; int row=t>>3, seg=t&7;
            int sb=(bm+row<o.M)?16:0;
            const float* src = sb ? (Ap+(long)(bm+row)*lda+kof+seg*4) : Ap;
            cpa16(sA + (unsigned)(((db*128+row)*36+seg*4)*4), src, sb);
        }
        if(!o.transB){
            #pragma unroll
            for(int i=0;i<2;i++){
                int t=tid*2+i; int kk=t>>4, seg=t&15;
                int rem=o.N-(bn+seg*4);
                int sb=rem>=4?16:(rem>0?rem*4:0);
                const float* src = sb ? (Bp+(long)(k0+kk)*o.ldB+bn+seg*4) : Bp;
                cpa16(sB + (unsigned)((db*2304 + kk*72+seg*4)*4), src, sb);
            }
        } else {
            #pragma unroll
            for(int i=0;i<2;i++){
                int t=tid*2+i; int nr=t>>3, seg=t&7;
                int sb=(bn+nr<o.N)?16:0;
                const float* src = sb ? (Bp+(long)(bn+nr)*o.ldB+k0+seg*4) : Bp;
                cpa16(sB + (unsigned)((db*2304 + nr*36+seg*4)*4), src, sb);
            }
        }
        asm volatile("cp.async.commit_group;":::"memory");
    };

    int np=o.K/32;
    issue(0,0);
    for(int p=0;p<np;p++){
        asm volatile("cp.async.wait_group 0;":::"memory");
        __syncthreads();
        if(p+1<np) issue(p+1,(p+1)&1);
        const float (*Af)[36]=(const float(*)[36])smf + (p&1)*128;
        const float* Bbuf=smf+9216+(p&1)*2304;
        #pragma unroll
        for(int kc=0;kc<32;kc+=8){
            // A1 frags (hi split)
            unsigned A1[2][4];
            float Araw[2][4];
            #pragma unroll
            for(int mt=0;mt<2;mt++)
                #pragma unroll
                for(int e=0;e<4;e++){
                    int kr=kc+(e>>1)*4+tg, mc=wm+mt*16+(e&1)*8+g;
                    float x=Af[mc][kr];
                    Araw[mt][e]=x;
                    A1[mt][e]=cvt_tf32(x);
                }
            // B1 frags (hi split), keep raw for lo
            unsigned B1[4][2];
            float Braw[4][2];
            #pragma unroll
            for(int nt=0;nt<4;nt++)
                #pragma unroll
                for(int e=0;e<2;e++){
                    int kr=kc+e*4+tg, nc=wn+nt*8+g;
                    float x = o.transB ? ((const float(*)[36])Bbuf)[nc][kr]
                                       : ((const float(*)[72])Bbuf)[kr][nc];
                    Braw[nt][e]=x;
                    B1[nt][e]=cvt_tf32(x);
                }
            // P1 = A1*B1
            #pragma unroll
            for(int mt=0;mt<2;mt++)
                #pragma unroll
                for(int nt=0;nt<4;nt++) MMA8(acc[mt][nt],A1[mt],B1[nt]);
            // P3 = A2f*B1
            {
                unsigned A2f[2][4];
                #pragma unroll
                for(int mt=0;mt<2;mt++)
                    #pragma unroll
                    for(int e=0;e<4;e++)
                        A2f[mt][e]=cvt_tf32(Araw[mt][e]-__uint_as_float(A1[mt][e]));
                #pragma unroll
                for(int mt=0;mt<2;mt++)
                    #pragma unroll
                    for(int nt=0;nt<4;nt++) MMA8(acc[mt][nt],A2f[mt],B1[nt]);
            }
            // P2 = A1*B2
            {
                unsigned B2[4][2];
                #pragma unroll
                for(int nt=0;nt<4;nt++)
                    #pragma unroll
                    for(int e=0;e<2;e++)
                        B2[nt][e]=cvt_tf32(Braw[nt][e]-__uint_as_float(B1[nt][e]));
                #pragma unroll
                for(int mt=0;mt<2;mt++)
                    #pragma unroll
                    for(int nt=0;nt<4;nt++) MMA8(acc[mt][nt],A1[mt],B2[nt]);
            }
        }
        __syncthreads();
    }

    // ---- epilogue ----
    #pragma unroll
    for(int mt=0;mt<2;mt++){
        #pragma unroll
        for(int nt=0;nt<4;nt++){
            #pragma unroll
            for(int half=0;half<2;half++){
                int gr=bm+wm+mt*16+half*8+g;
                if(gr>=o.M) continue;
                float v0=acc[mt][nt][half*2+0]*o.alpha;
                float v1=acc[mt][nt][half*2+1]*o.alpha;
                if(o.epi==1){
                    v0=((v0>0.f)?v0:expm1f(v0))+1.f;
                    v1=((v1>0.f)?v1:expm1f(v1))+1.f;
                } else if(o.epi==2){
                    v0=fmaxf(v0,0.f); v1=fmaxf(v1,0.f);
                }
                int gc=bn+wn+nt*8+tg*2;
                if(gc<o.N)   o.C[(long)gr*o.N+gc]=v0;
                if(gc+1<o.N) o.C[(long)gr*o.N+gc+1]=v1;
            }
        }
    }
}

// ---- KV reduce ----
__global__ void __launch_bounds__(256) kv_reduce_k(
    const float* __restrict__ Kp,const float* __restrict__ Vp,
    float* __restrict__ KV,float* __restrict__ Ksum,
    int Ls,int chunkRows,const int* __restrict__ counts)
{
    int nh=blockIdx.y; int n=nh>>3, h=nh&7;
    int cnt=counts?counts[n]:Ls; if(cnt>Ls) cnt=Ls;
    int rstart=blockIdx.x*chunkRows; if(rstart>=cnt) return;
    int rend=min(rstart+chunkRows,cnt);

    __shared__ float sK[32][33];
    __shared__ float sV[32][33];
    int tid=threadIdx.x;
    int d=tid>>3, vb=(tid&7)*4;
    float acc[4]={0,0,0,0}; float ksumAcc=0.f;
    long rowBase=(long)n*Ls;

    for(int r0=rstart;r0<rend;r0+=32){
        #pragma unroll
        for(int t=0;t<8;t++){
            int idx=tid+t*256; int rr=idx>>6, cc=idx&63;
            int grow=r0+rr; float val=0.f;
            if(grow<rend){
                long base=(rowBase+grow)*CDIM+h*32;
                val=(cc<32)?Kp[base+cc]:Vp[base+cc-32];
            }
            if(cc<32) sK[rr][cc]=val; else sV[rr][cc-32]=val;
        }
        __syncthreads();
        int nr=min(32,rend-r0);
        for(int r=0;r<nr;r++){
            float kv=sK[r][d];
            #pragma unroll
            for(int j=0;j<4;j++) acc[j]=fmaf(kv,sV[r][vb+j],acc[j]);
        }
        if(tid<32) for(int r=0;r<nr;r++) ksumAcc+=sK[r][tid];
        __syncthreads();
    }
    long ob=(long)nh*1024;
    #pragma unroll
    for(int j=0;j<4;j++) atomicAdd(&KV[ob+d*32+vb+j],acc[j]);
    if(tid<32) atomicAdd(&Ksum[(long)nh*32+tid],ksumAcc);
}

__global__ void __launch_bounds__(256) msg_k(
    const float* __restrict__ Q,const float* __restrict__ KV,
    const float* __restrict__ Ksum,float* __restrict__ Msg,
    int Lx,int nbS,const int* __restrict__ counts)
{
    int row=blockIdx.x; int n=row/Lx;
    if(counts && (row-n*Lx)>=counts[n]) return;
    int ns=n%nbS;
    __shared__ float qs[256]; __shared__ float zinv[8];
    int t=threadIdx.x;
    float qv=Q[(long)row*CDIM+t]; qs[t]=qv;
    int h=t>>5, lane=t&31;
    float p=qv*Ksum[(ns*8+h)*32+lane];
    #pragma unroll
    for(int o=16;o>0;o>>=1) p+=__shfl_xor_sync(0xffffffffu,p,o);
    if(lane==0) zinv[h]=1.f/(p+1e-6f);
    __syncthreads();
    const float* kvb=KV+(long)(ns*8+h)*1024;
    float acc=0.f;
    #pragma unroll
    for(int d=0;d<32;d++) acc=fmaf(qs[h*32+d],kvb[d*32+lane],acc);
    Msg[(long)row*CDIM+t]=acc*zinv[h];
}

__device__ __forceinline__ float blockSum256(float v,float* red){
    #pragma unroll
    for(int o=16;o>0;o>>=1) v+=__shfl_xor_sync(0xffffffffu,v,o);
    int t=threadIdx.x;
    if((t&31)==0) red[t>>5]=v;
    __syncthreads();
    float s=red[0]+red[1]+red[2]+red[3]+red[4]+red[5]+red[6]+red[7];
    __syncthreads();
    return s;
}
__global__ void __launch_bounds__(256) ln_k(
    const float* __restrict__ X,float* __restrict__ Y,float* __restrict__ addTo,
    int Lx,const int* __restrict__ counts,float eps)
{
    int row=blockIdx.x; int n=row/Lx;
    if(counts && (row-n*Lx)>=counts[n]) return;
    __shared__ float red[8];
    int t=threadIdx.x;
    long off=(long)row*CDIM+t;
    float v=X[off];
    float mu=blockSum256(v,red)*(1.f/256.f);
    float dv=v-mu;
    float var=blockSum256(dv*dv,red)*(1.f/256.f);
    float y=dv*rsqrtf(var+eps);
    if(addTo) addTo[off]+=y; else Y[off]=y;
}

// ======================= topic preprocessing =======================
__global__ void tm_k(const float* __restrict__ t0r,const float* __restrict__ t1r){
    int b=blockIdx.x; int n=b/NTOPIC, m=b%NTOPIC;
    int k=threadIdx.x; if(k>=NTOPIC) return;
    const float* p0=t0r+(long)n*96*NTOPIC;
    const float* p1=t1r+(long)n*96*NTOPIC;
    float s=0.f;
    for(int d=0;d<96;d++) s+=p0[d*NTOPIC+m]*p1[d*NTOPIC+k];
    g_tm[(long)b*NTOPIC+k]=floorf(s*0.0625f);
}
__global__ void colstat_k(){
    int n=blockIdx.x; int l=threadIdx.x; if(l>=NTOPIC) return;
    const float* p=g_tm+(long)n*NTOPIC*NTOPIC;
    float mx=-1e30f;
    for(int m=0;m<NTOPIC;m++) mx=fmaxf(mx,p[m*NTOPIC+l]);
    float s=0.f;
    for(int m=0;m<NTOPIC;m++) s+=expf(p[m*NTOPIC+l]-mx);
    g_cmax[n*NTOPIC+l]=mx; g_csum[n*NTOPIC+l]=s;
}
__global__ void tmidx_k(){
    if(threadIdx.x!=0) return;
    int b=blockIdx.x; int n=b/NTOPIC;
    const float* p=g_tm+(long)b*NTOPIC;
    float rmx=-1e30f;
    for(int l=0;l<NTOPIC;l++) rmx=fmaxf(rmx,p[l]);
    float rs=0.f;
    for(int l=0;l<NTOPIC;l++) rs+=expf(p[l]-rmx);
    float best=-1e30f; int bi=0;
    for(int l=0;l<NTOPIC;l++){
        float v=(expf(p[l]-rmx)/rs)*(expf(p[l]-g_cmax[n*NTOPIC+l])/g_csum[n*NTOPIC+l]);
        if(v>best){best=v;bi=l;}
    }
    g_tmidx[b]=bi;
}
__global__ void topic_k(const float* __restrict__ topic0,const float* __restrict__ topic1){
    int b=blockIdx.x; int n=b/NTOPIC, m=b%NTOPIC;
    int j=threadIdx.x; if(j>=96) return;
    int idx=g_tmidx[(NBATCH-1)*NTOPIC+m];
    float v;
    if(j<48){
        const float* p0=topic0+(long)n*96*NTOPIC;
        v=0.5f*(p0[(2*j)*NTOPIC+m]+p0[(2*j+1)*NTOPIC+m]);
    }else{
        int d0=2*j-96;
        const float* p1=topic1+(long)n*96*NTOPIC;
        v=0.5f*(p1[d0*NTOPIC+idx]+p1[(d0+1)*NTOPIC+idx]);
    }
    g_topic[(long)b*96+j]=v;
}
__global__ void __launch_bounds__(256) seedfin_k(){
    int row=blockIdx.x; int t=threadIdx.x;
    __shared__ float red[8];
    float v;
    if(t<160){
        int s=t*256/160;
        int e=((t+1)*256+159)/160;
        float acc=0.f;
        for(int i=s;i<e;i++) acc+=g_seeds[(long)row*CDIM+i];
        v=acc/(float)(e-s);
    }else v=g_topic[(long)row*96+(t-160)];
    float mu=blockSum256(v,red)*(1.f/256.f);
    float dv=v-mu;
    float var=blockSum256(dv*dv,red)*(1.f/256.f);
    g_seedsF[(long)row*CDIM+t]=dv*rsqrtf(var+1e-5f);
}

// ======================= dmatrix stats / selection =======================
__global__ void __launch_bounds__(64) prob_k(){
    __shared__ float s[NTOPIC];
    int t=threadIdx.x;
    for(int i=t;i<NTOPIC;i+=64) s[i]=0.f;
    __syncthreads();
    int row=blockIdx.x*64+t;
    const float* dr=g_dm+(long)row*NTOPIC;
    float mx=dr[0]; int ai=0;
    for(int k=1;k<NTOPIC;k++){ float v=dr[k]; if(v>mx){mx=v;ai=k;} }
    g_amax[row]=ai;
    float se=0.f;
    for(int k=0;k<NTOPIC;k++) se+=expf(dr[k]-mx);
    float inv=1.f/se;
    for(int kk=0;kk<NTOPIC;kk++){
        int k=(t+kk)%NTOPIC;
        atomicAdd(&s[k],expf(dr[k]-mx)*inv);
    }
    __syncthreads();
    int n=row/(2*LTOK);
    int half=(row%(2*LTOK))/LTOK;
    float* outp=g_sumh+((long)(half*NBATCH+n)*NTOPIC);
    for(int i=t;i<NTOPIC;i+=64) atomicAdd(&outp[i],s[i]);
}
__global__ void theta_k(){
    if(threadIdx.x!=0) return;
    int n=blockIdx.x;
    float a[NTOPIC],b[NTOPIC],th[NTOPIC];
    float sa=0.f,sb=0.f;
    for(int k=0;k<NTOPIC;k++){a[k]=g_sumh[(0*NBATCH+n)*NTOPIC+k];sa+=fabsf(a[k]);}
    for(int k=0;k<NTOPIC;k++){b[k]=g_sumh[(1*NBATCH+n)*NTOPIC+k];sb+=fabsf(b[k]);}
    sa=fmaxf(sa,1e-12f); sb=fmaxf(sb,1e-12f);
    for(int k=0;k<NTOPIC;k++) th[k]=(a[k]/sa)*(b[k]/sb);
    bool used[NTOPIC];
    for(int k=0;k<NTOPIC;k++) used[k]=false;
    for(int kk=0;kk<NSAMP;kk++){
        float best=-1e30f; int bi=0;
        for(int k=0;k<NTOPIC;k++) if(!used[k]&&th[k]>best){best=th[k];bi=k;}
        used[bi]=true; g_inds[n*NSAMP+kk]=bi;
    }
}
__global__ void selbuild_k(){
    if(threadIdx.x!=0) return;
    int b=blockIdx.x;
    int kk=b/(2*NBATCH);
    int half=(b/NBATCH)%2;
    int n=b%NBATCH;
    int topic=g_inds[n*NSAMP+kk];
    const int* am=g_amax+n*2*LTOK+half*LTOK;
    int c=0; int* sl=g_sel+(long)b*LTOK;
    for(int l=0;l<LTOK;l++) if(am[l]==topic) sl[c++]=l;
    g_cnt[b]=c;
}
__global__ void cond_k(){
    int kk=threadIdx.x; if(kk>=NSAMP) return;
    int s0=0,s1=0;
    for(int n=0;n<NBATCH;n++){
        s0+=g_cnt[(kk*2+0)*NBATCH+n];
        s1+=g_cnt[(kk*2+1)*NBATCH+n];
    }
    g_cond[kk]=(s0>0&&s1>0)?1.f:0.f;
}
__global__ void repack_cnt_k(){
    int i=threadIdx.x; if(i>=NBM) return;
    int half=i/(NSAMP*NBATCH);
    int r=i-half*(NSAMP*NBATCH);
    int kk=r/NBATCH, n=r%NBATCH;
    g_cntm[i]=g_cnt[(kk*2+half)*NBATCH+n];
}
__global__ void gatherM_k(const float* __restrict__ f0,const float* __restrict__ f1){
    int j=blockIdx.x, n=blockIdx.y, z=blockIdx.z;
    int half=z/NSAMP, kk=z-half*NSAMP;
    int slot=(kk*2+half)*NBATCH+n;
    if(j>=g_cnt[slot]) return;
    int l=g_sel[(long)slot*LTOK+j];
    const float* src = half? f1 : f0;
    int mb = half*(NSAMP*NBATCH)+kk*NBATCH+n;
    g_nf[((long)mb*LTOK+j)*CDIM+threadIdx.x]=src[((long)n*LTOK+l)*CDIM+threadIdx.x];
}
__global__ void scatterM_k(float* __restrict__ o0,float* __restrict__ o1){
    int j=blockIdx.x, n=blockIdx.y, z=blockIdx.z;
    int half=z/NSAMP, kk=z-half*NSAMP;
    int slot=(kk*2+half)*NBATCH+n;
    if(j>=g_cnt[slot]) return;
    int l=g_sel[(long)slot*LTOK+j];
    float* dst = half? o1 : o0;
    int mb = half*(NSAMP*NBATCH)+kk*NBATCH+n;
    float c=g_cond[kk];
    dst[((long)n*LTOK+l)*CDIM+threadIdx.x]+=g_nf[((long)mb*LTOK+j)*CDIM+threadIdx.x]*c;
}
__global__ void blend_k(float* __restrict__ outF,const float* __restrict__ fcur,int half){
    int r=blockIdx.x; int n=r/LTOK, l=r%LTOK;
    int am=g_amax[n*2*LTOK+half*LTOK+l];
    int issel=0;
    for(int kk=0;kk<NSAMP;kk++) if(am==g_inds[n*NSAMP+kk]) issel=1;
    if(!issel){
        int t=threadIdx.x;
        outF[(long)r*CDIM+t]+=fcur[(long)r*CDIM+t];
    }
}
__global__ void tmi_k(int half,float* __restrict__ out){
    int nk=blockIdx.x; int n=nk/NTOPIC, k=nk%NTOPIC;
    int h=blockIdx.y, w=threadIdx.x;
    const float* base=g_dm+(long)n*2*LTOK*NTOPIC+(long)half*LTOK*NTOPIC;
    float acc=0.f;
    for(int dh=-1;dh<=1;dh++){
        int hh=h+dh; if(hh<0||hh>=64) continue;
        for(int dw=-1;dw<=1;dw++){
            int ww=w+dw; if(ww<0||ww>=64) continue;
            acc+=base[k*4096+hh*64+ww];
        }
    }
    acc*=(1.f/9.f);
    int l=h*64+w;
    out[((long)n*LTOK+l)*NTOPIC+k]=base[(long)l*NTOPIC+k]*acc;
}

// ======================= host side =======================
static void g1(const GOp& o){
    dim3 g((o.N+63)/64,(o.M+127)/128,1);
    gemm_k<<<g,256,GEMM_SMEM>>>(o,o,o);
}
static void g3(const GOp& a,const GOp& b,const GOp& c){
    int mt=(a.M+127)/128;
    int t2=(b.M+127)/128; if(t2>mt) mt=t2;
    int t3=(c.M+127)/128; if(t3>mt) mt=t3;
    int nt=(a.N+63)/64;
    int n2=(b.N+63)/64; if(n2>nt) nt=n2;
    int n3=(c.N+63)/64; if(n3>nt) nt=n3;
    dim3 g(nt,mt,3);
    gemm_k<<<g,256,GEMM_SMEM>>>(a,b,c);
}

struct Ptrs {
    float *f,*fo,*seeds,*seedsF,*nf,*q,*k,*v,*hid,*ffn,*KV,*Ksum,*dm,*sumh;
    int *cntm;
};

static void enc_layer(Ptrs& P,float* x,const float* src,int nbX,int rpbX,int nbS,int rpbS,
                      const int* cx,const int* cs,
                      const float* Wq,const float* Wk,const float* Wv,
                      const float* Wm,const float* W1,const float* W2)
{
    int Mx=nbX*rpbX, Ms=nbS*rpbS;
    float* msg=P.q;
    GOp oq{x,  nullptr,Wq,P.q, Mx,256,256,0,256,0L,rpbX,cx,1.f,1};
    GOp ok{src,nullptr,Wk,P.k, Ms,256,256,0,256,0L,rpbS,cs,1.f,1};
    GOp ov{src,nullptr,Wv,P.v, Ms,256,256,0,256,0L,rpbS,cs,1.f,0};
    g3(oq,ok,ov);
    long kvN=(long)nbS*NHEAD*1024, ksN=(long)nbS*NHEAD*32;
    zero2_k<<<(int)((kvN+255)/256),256>>>(P.KV,kvN,P.Ksum,ksN);
    dim3 gkv((rpbS+511)/512,nbS*NHEAD);
    kv_reduce_k<<<gkv,256>>>(P.k,P.v,P.KV,P.Ksum,rpbS,512,cs);
    msg_k<<<Mx,256>>>(P.q,P.KV,P.Ksum,msg,rpbX,nbS,cx);
    GOp om{msg,nullptr,Wm,P.ffn, Mx,256,256,0,256,0L,rpbX,cx,1.f,0};
    g1(om);
    ln_k<<<Mx,256>>>(P.ffn,msg,nullptr,rpbX,cx,1e-5f);
    GOp oh{x,msg,W1,P.hid, Mx,512,512,0,512,0L,rpbX,cx,1.f,2};
    g1(oh);
    GOp of{P.hid,nullptr,W2,P.ffn, Mx,256,512,0,256,0L,rpbX,cx,1.f,0};
    g1(of);
    ln_k<<<Mx,256>>>(P.ffn,nullptr,x,rpbX,cx,1e-5f);
}

extern "C" void kernel_launch(void* const* d_in, const int* in_sizes, int n_in,
                              void* d_out, int out_size)
{
    static Ptrs P; static bool inited=false;
    if(!inited){
        cudaGetSymbolAddress((void**)&P.f,g_f);
        cudaGetSymbolAddress((void**)&P.fo,g_fo);
        cudaGetSymbolAddress((void**)&P.seeds,g_seeds);
        cudaGetSymbolAddress((void**)&P.seedsF,g_seedsF);
        cudaGetSymbolAddress((void**)&P.nf,g_nf);
        cudaGetSymbolAddress((void**)&P.q,g_q);
        cudaGetSymbolAddress((void**)&P.k,g_k);
        cudaGetSymbolAddress((void**)&P.v,g_v);
        cudaGetSymbolAddress((void**)&P.hid,g_hid);
        cudaGetSymbolAddress((void**)&P.ffn,g_ffn);
        cudaGetSymbolAddress((void**)&P.KV,g_KV);
        cudaGetSymbolAddress((void**)&P.Ksum,g_Ksum);
        cudaGetSymbolAddress((void**)&P.dm,g_dm);
        cudaGetSymbolAddress((void**)&P.sumh,g_sumh);
        cudaGetSymbolAddress((void**)&P.cntm,g_cntm);
        cudaFuncSetAttribute(gemm_k,cudaFuncAttributeMaxDynamicSharedMemorySize,GEMM_SMEM);
        inited=true;
    }
    const float* in_f0=(const float*)d_in[0];
    const float* in_f1=(const float*)d_in[1];
    const float* in_t0=(const float*)d_in[2];
    const float* in_t1=(const float*)d_in[3];
    const float* in_st=(const float*)d_in[4];
    const float* Wq=(const float*)d_in[5];
    const float* Wk=(const float*)d_in[6];
    const float* Wv=(const float*)d_in[7];
    const float* Wm=(const float*)d_in[8];
    const float* W1=(const float*)d_in[9];
    const float* W2=(const float*)d_in[10];
    float* out=(float*)d_out;

    const long FREG=(long)NBATCH*LTOK*CDIM;
    const long TREG=(long)NBATCH*LTOK*NTOPIC;
    float* out_f0=out;
    float* out_f1=out+FREG;
    float* out_t0=out+2*FREG;
    float* out_t1=out+2*FREG+TREG;
    float* f0=P.f;
    float* f1=P.f+FREG;

    auto LW=[&](int i,const float*& wq,const float*& wk,const float*& wv,
                const float*& wm,const float*& w1,const float*& w2){
        wq=Wq+(long)i*256*256; wk=Wk+(long)i*256*256; wv=Wv+(long)i*256*256;
        wm=Wm+(long)i*256*256; w1=W1+(long)i*512*512; w2=W2+(long)i*512*256;
    };
    const float *wq,*wk,*wv,*wm,*w1,*w2;

    concatfeat_k<<<(int)((2*FREG+255)/256),256>>>(in_f0,in_f1);
    bcast_seeds_k<<<(NBATCH*NTOPIC*CDIM+255)/256,256>>>(in_st);
    tm_k<<<NBATCH*NTOPIC,128>>>(in_t0,in_t1);

    LW(0,wq,wk,wv,wm,w1,w2);
    enc_layer(P,P.seeds,P.fo,NBATCH,NTOPIC,NBATCH,2*LTOK,nullptr,nullptr,wq,wk,wv,wm,w1,w2);

    copy_k<<<(int)((FREG+255)/256),256>>>(f0,in_f0,FREG);
    copy_k<<<(int)((FREG+255)/256),256>>>(f1,in_f1,FREG);
    colstat_k<<<NBATCH,128>>>();
    tmidx_k<<<NBATCH*NTOPIC,32>>>();
    topic_k<<<NBATCH*NTOPIC,96>>>(in_t0,in_t1);

    LW(1,wq,wk,wv,wm,w1,w2);
    enc_layer(P,P.f,P.seeds,2*NBATCH,LTOK,NBATCH,NTOPIC,nullptr,nullptr,wq,wk,wv,wm,w1,w2);
    LW(2,wq,wk,wv,wm,w1,w2);
    enc_layer(P,P.seeds,P.fo,NBATCH,NTOPIC,NBATCH,2*LTOK,nullptr,nullptr,wq,wk,wv,wm,w1,w2);
    LW(3,wq,wk,wv,wm,w1,w2);
    enc_layer(P,P.f,P.seeds,2*NBATCH,LTOK,NBATCH,NTOPIC,nullptr,nullptr,wq,wk,wv,wm,w1,w2);

    seedfin_k<<<NBATCH*NTOPIC,256>>>();
    GOp od{P.fo,nullptr,P.seedsF,P.dm, NBATCH*2*LTOK,NTOPIC,256, 1,256,(long)NTOPIC*256, 2*LTOK,nullptr,0.0625f,0};
    g1(od);

    zero_k<<<(2*NBATCH*NTOPIC+255)/256,256>>>(P.sumh,2*NBATCH*NTOPIC);
    prob_k<<<(NBATCH*2*LTOK)/64,64>>>();
    theta_k<<<NBATCH,32>>>();
    selbuild_k<<<NSAMP*2*NBATCH,32>>>();
    cond_k<<<1,32>>>();
    repack_cnt_k<<<1,64>>>();

    zero_k<<<(int)((2*FREG+255)/256),256>>>(out_f0,2*FREG);

    float* nfA=P.nf;
    float* nfB=P.nf+(long)(NSAMP*NBATCH)*LTOK*CDIM;
    const int* cm =P.cntm;
    const int* cm0=P.cntm;
    const int* cm1=P.cntm+NSAMP*NBATCH;
    gatherM_k<<<dim3(LTOK,NBATCH,2*NSAMP),256>>>(f0,f1);
    for(int idt=0;idt<2;idt++){
        const float *aq,*ak,*av,*am,*a1,*a2,*bq,*bk,*bv,*bm,*b1,*b2;
        LW(4+idt*2,aq,ak,av,am,a1,a2);
        LW(5+idt*2,bq,bk,bv,bm,b1,b2);
        enc_layer(P,P.nf,P.nf,NBM,LTOK,NBM,LTOK,cm,cm,aq,ak,av,am,a1,a2);
        enc_layer(P,nfA,nfB,NSAMP*NBATCH,LTOK,NSAMP*NBATCH,LTOK,cm0,cm1,bq,bk,bv,bm,b1,b2);
        enc_layer(P,nfB,nfA,NSAMP*NBATCH,LTOK,NSAMP*NBATCH,LTOK,cm1,cm0,bq,bk,bv,bm,b1,b2);
    }
    scatterM_k<<<dim3(LTOK,NBATCH,2*NSAMP),256>>>(out_f0,out_f1);

    blend_k<<<NBATCH*LTOK,256>>>(out_f0,f0,0);
    blend_k<<<NBATCH*LTOK,256>>>(out_f1,f1,1);
    tmi_k<<<dim3(NBATCH*NTOPIC,64),64>>>(0,out_t0);
    tmi_k<<<dim3(NBATCH*NTOPIC,64),64>>>(1,out_t1);
}

// round 16
// speedup vs baseline: 1.5962x; 1.5962x over previous
#include <cuda_runtime.h>
#include <math.h>

#define NBATCH 4
#define LTOK   4096
#define CDIM   256
#define NHEAD  8
#define NTOPIC 100
#define NSAMP  6
#define NBM    48

typedef unsigned long long ull;

// ======================= device scratch =======================
__device__ float g_f[2*NBATCH*LTOK*CDIM];
__device__ float g_fo[NBATCH*2*LTOK*CDIM];
__device__ float g_seeds[NBATCH*NTOPIC*CDIM];
__device__ float g_seedsF[NBATCH*NTOPIC*CDIM];
__device__ float g_nf[NBM*LTOK*CDIM];
__device__ float g_q[NBM*LTOK*CDIM];
__device__ float g_k[NBM*LTOK*CDIM];
__device__ float g_v[NBM*LTOK*CDIM];
__device__ float g_hid[NBM*LTOK*2*CDIM];
__device__ float g_ffn[NBM*LTOK*CDIM];
__device__ float g_KV[NBM*NHEAD*32*32];
__device__ float g_Ksum[NBM*NHEAD*32];
__device__ float g_dm[NBATCH*2*LTOK*NTOPIC];
__device__ float g_tm[NBATCH*NTOPIC*NTOPIC];
__device__ float g_cmax[NBATCH*NTOPIC];
__device__ float g_csum[NBATCH*NTOPIC];
__device__ float g_topic[NBATCH*NTOPIC*96];
__device__ float g_sumh[2*NBATCH*NTOPIC];
__device__ float g_cond[NSAMP];
__device__ int   g_amax[NBATCH*2*LTOK];
__device__ int   g_tmidx[NBATCH*NTOPIC];
__device__ int   g_inds[NBATCH*NSAMP];
__device__ int   g_sel[2*NSAMP*NBATCH*LTOK];
__device__ int   g_cnt[2*NSAMP*NBATCH];
__device__ int   g_cntm[NBM];

// ======================= generic =======================
__global__ void zero_k(float* p, long n){
    long i=(long)blockIdx.x*blockDim.x+threadIdx.x; if(i<n) p[i]=0.f;
}
__global__ void zero2_k(float* p1, long n1, float* p2, long n2){
    long i=(long)blockIdx.x*blockDim.x+threadIdx.x;
    if(i<n1) p1[i]=0.f;
    if(i<n2) p2[i]=0.f;
}
__global__ void copy_k(float* d, const float* s, long n){
    long i=(long)blockIdx.x*blockDim.x+threadIdx.x; if(i<n) d[i]=s[i];
}
__global__ void bcast_seeds_k(const float* st){
    long i=(long)blockIdx.x*blockDim.x+threadIdx.x;
    long tot=(long)NBATCH*NTOPIC*CDIM;
    if(i<tot) g_seeds[i]=st[i%(NTOPIC*CDIM)];
}
__global__ void concatfeat_k(const float* f0, const float* f1){
    long i=(long)blockIdx.x*blockDim.x+threadIdx.x;
    long tot=(long)NBATCH*2*LTOK*CDIM; if(i>=tot) return;
    int n=(int)(i/(2L*LTOK*CDIM));
    long rem=i-(long)n*2*LTOK*CDIM;
    int row=(int)(rem/CDIM); int c=(int)(rem-(long)row*CDIM);
    if(row<LTOK) g_fo[i]=f0[((long)n*LTOK+row)*CDIM+c];
    else         g_fo[i]=f1[((long)n*LTOK+row-LTOK)*CDIM+c];
}

// ======================= GEMM: 128x64, tf32 mma 3-product (mask-split) =======================
struct GOp {
    const float* A; const float* A2; const float* B; float* C;
    int M,N,K,transB,ldB; long strideB; int rpb; const int* counts; float alpha; int epi;
};

#define GEMM_SMEM ((2*32*132 + 2*32*68)*4)   // 51.2 KB dynamic (double-buffered)

// tf32 split by mantissa mask: hi = x with low 13 bits cleared (valid tf32),
// lo = x - hi (exact; its top 10 mantissa bits are what the MMA reads).
__device__ __forceinline__ void msplit(float x,unsigned& hi,unsigned& lo){
    unsigned h=__float_as_uint(x)&0xFFFFE000u;
    hi=h;
    lo=__float_as_uint(x-__uint_as_float(h));
}
#define MMA8(c,a,b) asm volatile( \
    "mma.sync.aligned.m16n8k8.row.col.f32.tf32.tf32.f32 {%0,%1,%2,%3},{%4,%5,%6,%7},{%8,%9},{%0,%1,%2,%3};" \
    :"+f"(c[0]),"+f"(c[1]),"+f"(c[2]),"+f"(c[3]) \
    :"r"(a[0]),"r"(a[1]),"r"(a[2]),"r"(a[3]),"r"(b[0]),"r"(b[1]))

__global__ void __launch_bounds__(256,2) gemm_k(GOp o0, GOp o1, GOp o2)
{
    GOp o = (blockIdx.z==0)?o0:((blockIdx.z==1)?o1:o2);
    int bm=blockIdx.y*128, bn=blockIdx.x*64;
    if(bm>=o.M || bn>=o.N) return;
    if(o.counts){ int nb=bm/o.rpb; if(bm-nb*o.rpb>=o.counts[nb]) return; }
    const float* Bp = o.B + (o.strideB ? (long)(bm/o.rpb)*o.strideB : 0);
    int lda = o.A2 ? 256 : o.K;

    extern __shared__ float sm[];
    float (*AsBuf)[132] = (float(*)[132])sm;
    float (*BsBuf)[68]  = (float(*)[68])(sm + 2*32*132);

    int tid=threadIdx.x;
    int wid=tid>>5, lid=tid&31;
    int g=lid>>2, tg=lid&3;
    int wm=(wid&3)*32, wn=(wid>>2)*32;

    float acc[2][4][4];
    #pragma unroll
    for(int mt=0;mt<2;mt++)
        #pragma unroll
        for(int nt=0;nt<4;nt++)
            #pragma unroll
            for(int e=0;e<4;e++) acc[mt][nt][e]=0.f;

    int amm=tid>>1, akb=(tid&1)*16;
    bool arok = (bm+amm)<o.M;
    float ra[16], rb[8];

    auto loadA=[&](int k0){
        const float* Ap; int kof;
        if(o.A2 && k0>=256){ Ap=o.A2; kof=k0-256; } else { Ap=o.A; kof=k0; }
        if(arok){
            const float* s=Ap+(long)(bm+amm)*lda+kof+akb;
            float4 t0=*(const float4*)s;
            float4 t1=*(const float4*)(s+4);
            float4 t2=*(const float4*)(s+8);
            float4 t3=*(const float4*)(s+12);
            ra[0]=t0.x;ra[1]=t0.y;ra[2]=t0.z;ra[3]=t0.w;
            ra[4]=t1.x;ra[5]=t1.y;ra[6]=t1.z;ra[7]=t1.w;
            ra[8]=t2.x;ra[9]=t2.y;ra[10]=t2.z;ra[11]=t2.w;
            ra[12]=t3.x;ra[13]=t3.y;ra[14]=t3.z;ra[15]=t3.w;
        } else {
            #pragma unroll
            for(int j=0;j<16;j++) ra[j]=0.f;
        }
    };
    auto loadB=[&](int k0){
        if(!o.transB){
            int kk=tid>>3, nn=(tid&7)*8;
            const float* s=Bp+(long)(k0+kk)*o.ldB+bn+nn;
            if(bn+nn+7<o.N){
                float4 t0=*(const float4*)s;
                float4 t1=*(const float4*)(s+4);
                rb[0]=t0.x;rb[1]=t0.y;rb[2]=t0.z;rb[3]=t0.w;
                rb[4]=t1.x;rb[5]=t1.y;rb[6]=t1.z;rb[7]=t1.w;
            } else {
                #pragma unroll
                for(int j=0;j<8;j++) rb[j]=(bn+nn+j<o.N)?s[j]:0.f;
            }
        } else {
            int nn=tid>>2, kkl=(tid&3)*8;
            if(bn+nn<o.N){
                const float* s=Bp+(long)(bn+nn)*o.ldB+k0+kkl;
                float4 t0=*(const float4*)s;
                float4 t1=*(const float4*)(s+4);
                rb[0]=t0.x;rb[1]=t0.y;rb[2]=t0.z;rb[3]=t0.w;
                rb[4]=t1.x;rb[5]=t1.y;rb[6]=t1.z;rb[7]=t1.w;
            } else {
                #pragma unroll
                for(int j=0;j<8;j++) rb[j]=0.f;
            }
        }
    };
    auto storeA=[&](int db){
        float (*As)[132]=AsBuf+db*32;
        #pragma unroll
        for(int j=0;j<16;j++) As[akb+j][amm]=ra[j];
    };
    auto storeB=[&](int db){
        float (*Bs)[68]=BsBuf+db*32;
        if(!o.transB){
            int kk=tid>>3, nn=(tid&7)*8;
            *(float4*)&Bs[kk][nn]  =make_float4(rb[0],rb[1],rb[2],rb[3]);
            *(float4*)&Bs[kk][nn+4]=make_float4(rb[4],rb[5],rb[6],rb[7]);
        } else {
            int nn=tid>>2, kkl=(tid&3)*8;
            #pragma unroll
            for(int j=0;j<8;j++) Bs[kkl+j][nn]=rb[j];
        }
    };

    int np=o.K/32;
    loadA(0); loadB(0);
    storeA(0); storeB(0);

    for(int p=0;p<np;p++){
        __syncthreads();
        if(p+1<np){ loadA((p+1)*32); loadB((p+1)*32); }
        float (*As)[132]=AsBuf+(p&1)*32;
        float (*Bs)[68] =BsBuf+(p&1)*32;
        #pragma unroll
        for(int kc=0;kc<32;kc+=8){
            unsigned A1[2][4],A2f[2][4];
            #pragma unroll
            for(int mt=0;mt<2;mt++)
                #pragma unroll
                for(int e=0;e<4;e++){
                    float x=As[kc+(e>>1)*4+tg][wm+mt*16+(e&1)*8+g];
                    msplit(x,A1[mt][e],A2f[mt][e]);
                }
            unsigned B1[4][2],B2[4][2];
            #pragma unroll
            for(int nt=0;nt<4;nt++)
                #pragma unroll
                for(int e=0;e<2;e++){
                    float x=Bs[kc+e*4+tg][wn+nt*8+g];
                    msplit(x,B1[nt][e],B2[nt][e]);
                }
            #pragma unroll
            for(int mt=0;mt<2;mt++)
                #pragma unroll
                for(int nt=0;nt<4;nt++){
                    float* c=acc[mt][nt];
                    MMA8(c,A1[mt],B1[nt]);
                    MMA8(c,A1[mt],B2[nt]);
                    MMA8(c,A2f[mt],B1[nt]);
                }
        }
        if(p+1<np){ storeA((p+1)&1); storeB((p+1)&1); }
    }

    // ---- epilogue ----
    #pragma unroll
    for(int mt=0;mt<2;mt++){
        #pragma unroll
        for(int nt=0;nt<4;nt++){
            #pragma unroll
            for(int half=0;half<2;half++){
                int gr=bm+wm+mt*16+half*8+g;
                if(gr>=o.M) continue;
                float v0=acc[mt][nt][half*2+0]*o.alpha;
                float v1=acc[mt][nt][half*2+1]*o.alpha;
                if(o.epi==1){
                    v0=((v0>0.f)?v0:expm1f(v0))+1.f;
                    v1=((v1>0.f)?v1:expm1f(v1))+1.f;
                } else if(o.epi==2){
                    v0=fmaxf(v0,0.f); v1=fmaxf(v1,0.f);
                }
                int gc=bn+wn+nt*8+tg*2;
                if(gc<o.N)   o.C[(long)gr*o.N+gc]=v0;
                if(gc+1<o.N) o.C[(long)gr*o.N+gc+1]=v1;
            }
        }
    }
}

// ---- KV reduce ----
__global__ void __launch_bounds__(256) kv_reduce_k(
    const float* __restrict__ Kp,const float* __restrict__ Vp,
    float* __restrict__ KV,float* __restrict__ Ksum,
    int Ls,int chunkRows,const int* __restrict__ counts)
{
    int nh=blockIdx.y; int n=nh>>3, h=nh&7;
    int cnt=counts?counts[n]:Ls; if(cnt>Ls) cnt=Ls;
    int rstart=blockIdx.x*chunkRows; if(rstart>=cnt) return;
    int rend=min(rstart+chunkRows,cnt);

    __shared__ float sK[32][33];
    __shared__ float sV[32][33];
    int tid=threadIdx.x;
    int d=tid>>3, vb=(tid&7)*4;
    float acc[4]={0,0,0,0}; float ksumAcc=0.f;
    long rowBase=(long)n*Ls;

    for(int r0=rstart;r0<rend;r0+=32){
        #pragma unroll
        for(int t=0;t<8;t++){
            int idx=tid+t*256; int rr=idx>>6, cc=idx&63;
            int grow=r0+rr; float val=0.f;
            if(grow<rend){
                long base=(rowBase+grow)*CDIM+h*32;
                val=(cc<32)?Kp[base+cc]:Vp[base+cc-32];
            }
            if(cc<32) sK[rr][cc]=val; else sV[rr][cc-32]=val;
        }
        __syncthreads();
        int nr=min(32,rend-r0);
        for(int r=0;r<nr;r++){
            float kv=sK[r][d];
            #pragma unroll
            for(int j=0;j<4;j++) acc[j]=fmaf(kv,sV[r][vb+j],acc[j]);
        }
        if(tid<32) for(int r=0;r<nr;r++) ksumAcc+=sK[r][tid];
        __syncthreads();
    }
    long ob=(long)nh*1024;
    #pragma unroll
    for(int j=0;j<4;j++) atomicAdd(&KV[ob+d*32+vb+j],acc[j]);
    if(tid<32) atomicAdd(&Ksum[(long)nh*32+tid],ksumAcc);
}

__global__ void __launch_bounds__(256) msg_k(
    const float* __restrict__ Q,const float* __restrict__ KV,
    const float* __restrict__ Ksum,float* __restrict__ Msg,
    int Lx,int nbS,const int* __restrict__ counts)
{
    int row=blockIdx.x; int n=row/Lx;
    if(counts && (row-n*Lx)>=counts[n]) return;
    int ns=n%nbS;
    __shared__ float qs[256]; __shared__ float zinv[8];
    int t=threadIdx.x;
    float qv=Q[(long)row*CDIM+t]; qs[t]=qv;
    int h=t>>5, lane=t&31;
    float p=qv*Ksum[(ns*8+h)*32+lane];
    #pragma unroll
    for(int o=16;o>0;o>>=1) p+=__shfl_xor_sync(0xffffffffu,p,o);
    if(lane==0) zinv[h]=1.f/(p+1e-6f);
    __syncthreads();
    const float* kvb=KV+(long)(ns*8+h)*1024;
    float acc=0.f;
    #pragma unroll
    for(int d=0;d<32;d++) acc=fmaf(qs[h*32+d],kvb[d*32+lane],acc);
    Msg[(long)row*CDIM+t]=acc*zinv[h];
}

__device__ __forceinline__ float blockSum256(float v,float* red){
    #pragma unroll
    for(int o=16;o>0;o>>=1) v+=__shfl_xor_sync(0xffffffffu,v,o);
    int t=threadIdx.x;
    if((t&31)==0) red[t>>5]=v;
    __syncthreads();
    float s=red[0]+red[1]+red[2]+red[3]+red[4]+red[5]+red[6]+red[7];
    __syncthreads();
    return s;
}
__global__ void __launch_bounds__(256) ln_k(
    const float* __restrict__ X,float* __restrict__ Y,float* __restrict__ addTo,
    int Lx,const int* __restrict__ counts,float eps)
{
    int row=blockIdx.x; int n=row/Lx;
    if(counts && (row-n*Lx)>=counts[n]) return;
    __shared__ float red[8];
    int t=threadIdx.x;
    long off=(long)row*CDIM+t;
    float v=X[off];
    float mu=blockSum256(v,red)*(1.f/256.f);
    float dv=v-mu;
    float var=blockSum256(dv*dv,red)*(1.f/256.f);
    float y=dv*rsqrtf(var+eps);
    if(addTo) addTo[off]+=y; else Y[off]=y;
}

// ======================= topic preprocessing =======================
__global__ void tm_k(const float* __restrict__ t0r,const float* __restrict__ t1r){
    int b=blockIdx.x; int n=b/NTOPIC, m=b%NTOPIC;
    int k=threadIdx.x; if(k>=NTOPIC) return;
    const float* p0=t0r+(long)n*96*NTOPIC;
    const float* p1=t1r+(long)n*96*NTOPIC;
    float s=0.f;
    for(int d=0;d<96;d++) s+=p0[d*NTOPIC+m]*p1[d*NTOPIC+k];
    g_tm[(long)b*NTOPIC+k]=floorf(s*0.0625f);
}
__global__ void colstat_k(){
    int n=blockIdx.x; int l=threadIdx.x; if(l>=NTOPIC) return;
    const float* p=g_tm+(long)n*NTOPIC*NTOPIC;
    float mx=-1e30f;
    for(int m=0;m<NTOPIC;m++) mx=fmaxf(mx,p[m*NTOPIC+l]);
    float s=0.f;
    for(int m=0;m<NTOPIC;m++) s+=expf(p[m*NTOPIC+l]-mx);
    g_cmax[n*NTOPIC+l]=mx; g_csum[n*NTOPIC+l]=s;
}
__global__ void tmidx_k(){
    if(threadIdx.x!=0) return;
    int b=blockIdx.x; int n=b/NTOPIC;
    const float* p=g_tm+(long)b*NTOPIC;
    float rmx=-1e30f;
    for(int l=0;l<NTOPIC;l++) rmx=fmaxf(rmx,p[l]);
    float rs=0.f;
    for(int l=0;l<NTOPIC;l++) rs+=expf(p[l]-rmx);
    float best=-1e30f; int bi=0;
    for(int l=0;l<NTOPIC;l++){
        float v=(expf(p[l]-rmx)/rs)*(expf(p[l]-g_cmax[n*NTOPIC+l])/g_csum[n*NTOPIC+l]);
        if(v>best){best=v;bi=l;}
    }
    g_tmidx[b]=bi;
}
__global__ void topic_k(const float* __restrict__ topic0,const float* __restrict__ topic1){
    int b=blockIdx.x; int n=b/NTOPIC, m=b%NTOPIC;
    int j=threadIdx.x; if(j>=96) return;
    int idx=g_tmidx[(NBATCH-1)*NTOPIC+m];
    float v;
    if(j<48){
        const float* p0=topic0+(long)n*96*NTOPIC;
        v=0.5f*(p0[(2*j)*NTOPIC+m]+p0[(2*j+1)*NTOPIC+m]);
    }else{
        int d0=2*j-96;
        const float* p1=topic1+(long)n*96*NTOPIC;
        v=0.5f*(p1[d0*NTOPIC+idx]+p1[(d0+1)*NTOPIC+idx]);
    }
    g_topic[(long)b*96+j]=v;
}
__global__ void __launch_bounds__(256) seedfin_k(){
    int row=blockIdx.x; int t=threadIdx.x;
    __shared__ float red[8];
    float v;
    if(t<160){
        int s=t*256/160;
        int e=((t+1)*256+159)/160;
        float acc=0.f;
        for(int i=s;i<e;i++) acc+=g_seeds[(long)row*CDIM+i];
        v=acc/(float)(e-s);
    }else v=g_topic[(long)row*96+(t-160)];
    float mu=blockSum256(v,red)*(1.f/256.f);
    float dv=v-mu;
    float var=blockSum256(dv*dv,red)*(1.f/256.f);
    g_seedsF[(long)row*CDIM+t]=dv*rsqrtf(var+1e-5f);
}

// ======================= dmatrix stats / selection =======================
__global__ void __launch_bounds__(64) prob_k(){
    __shared__ float s[NTOPIC];
    int t=threadIdx.x;
    for(int i=t;i<NTOPIC;i+=64) s[i]=0.f;
    __syncthreads();
    int row=blockIdx.x*64+t;
    const float* dr=g_dm+(long)row*NTOPIC;
    float mx=dr[0]; int ai=0;
    for(int k=1;k<NTOPIC;k++){ float v=dr[k]; if(v>mx){mx=v;ai=k;} }
    g_amax[row]=ai;
    float se=0.f;
    for(int k=0;k<NTOPIC;k++) se+=expf(dr[k]-mx);
    float inv=1.f/se;
    for(int kk=0;kk<NTOPIC;kk++){
        int k=(t+kk)%NTOPIC;
        atomicAdd(&s[k],expf(dr[k]-mx)*inv);
    }
    __syncthreads();
    int n=row/(2*LTOK);
    int half=(row%(2*LTOK))/LTOK;
    float* outp=g_sumh+((long)(half*NBATCH+n)*NTOPIC);
    for(int i=t;i<NTOPIC;i+=64) atomicAdd(&outp[i],s[i]);
}
__global__ void theta_k(){
    if(threadIdx.x!=0) return;
    int n=blockIdx.x;
    float a[NTOPIC],b[NTOPIC],th[NTOPIC];
    float sa=0.f,sb=0.f;
    for(int k=0;k<NTOPIC;k++){a[k]=g_sumh[(0*NBATCH+n)*NTOPIC+k];sa+=fabsf(a[k]);}
    for(int k=0;k<NTOPIC;k++){b[k]=g_sumh[(1*NBATCH+n)*NTOPIC+k];sb+=fabsf(b[k]);}
    sa=fmaxf(sa,1e-12f); sb=fmaxf(sb,1e-12f);
    for(int k=0;k<NTOPIC;k++) th[k]=(a[k]/sa)*(b[k]/sb);
    bool used[NTOPIC];
    for(int k=0;k<NTOPIC;k++) used[k]=false;
    for(int kk=0;kk<NSAMP;kk++){
        float best=-1e30f; int bi=0;
        for(int k=0;k<NTOPIC;k++) if(!used[k]&&th[k]>best){best=th[k];bi=k;}
        used[bi]=true; g_inds[n*NSAMP+kk]=bi;
    }
}
__global__ void selbuild_k(){
    if(threadIdx.x!=0) return;
    int b=blockIdx.x;
    int kk=b/(2*NBATCH);
    int half=(b/NBATCH)%2;
    int n=b%NBATCH;
    int topic=g_inds[n*NSAMP+kk];
    const int* am=g_amax+n*2*LTOK+half*LTOK;
    int c=0; int* sl=g_sel+(long)b*LTOK;
    for(int l=0;l<LTOK;l++) if(am[l]==topic) sl[c++]=l;
    g_cnt[b]=c;
}
__global__ void cond_k(){
    int kk=threadIdx.x; if(kk>=NSAMP) return;
    int s0=0,s1=0;
    for(int n=0;n<NBATCH;n++){
        s0+=g_cnt[(kk*2+0)*NBATCH+n];
        s1+=g_cnt[(kk*2+1)*NBATCH+n];
    }
    g_cond[kk]=(s0>0&&s1>0)?1.f:0.f;
}
__global__ void repack_cnt_k(){
    int i=threadIdx.x; if(i>=NBM) return;
    int half=i/(NSAMP*NBATCH);
    int r=i-half*(NSAMP*NBATCH);
    int kk=r/NBATCH, n=r%NBATCH;
    g_cntm[i]=g_cnt[(kk*2+half)*NBATCH+n];
}
__global__ void gatherM_k(const float* __restrict__ f0,const float* __restrict__ f1){
    int j=blockIdx.x, n=blockIdx.y, z=blockIdx.z;
    int half=z/NSAMP, kk=z-half*NSAMP;
    int slot=(kk*2+half)*NBATCH+n;
    if(j>=g_cnt[slot]) return;
    int l=g_sel[(long)slot*LTOK+j];
    const float* src = half? f1 : f0;
    int mb = half*(NSAMP*NBATCH)+kk*NBATCH+n;
    g_nf[((long)mb*LTOK+j)*CDIM+threadIdx.x]=src[((long)n*LTOK+l)*CDIM+threadIdx.x];
}
__global__ void scatterM_k(float* __restrict__ o0,float* __restrict__ o1){
    int j=blockIdx.x, n=blockIdx.y, z=blockIdx.z;
    int half=z/NSAMP, kk=z-half*NSAMP;
    int slot=(kk*2+half)*NBATCH+n;
    if(j>=g_cnt[slot]) return;
    int l=g_sel[(long)slot*LTOK+j];
    float* dst = half? o1 : o0;
    int mb = half*(NSAMP*NBATCH)+kk*NBATCH+n;
    float c=g_cond[kk];
    dst[((long)n*LTOK+l)*CDIM+threadIdx.x]+=g_nf[((long)mb*LTOK+j)*CDIM+threadIdx.x]*c;
}
__global__ void blend_k(float* __restrict__ outF,const float* __restrict__ fcur,int half){
    int r=blockIdx.x; int n=r/LTOK, l=r%LTOK;
    int am=g_amax[n*2*LTOK+half*LTOK+l];
    int issel=0;
    for(int kk=0;kk<NSAMP;kk++) if(am==g_inds[n*NSAMP+kk]) issel=1;
    if(!issel){
        int t=threadIdx.x;
        outF[(long)r*CDIM+t]+=fcur[(long)r*CDIM+t];
    }
}
__global__ void tmi_k(int half,float* __restrict__ out){
    int nk=blockIdx.x; int n=nk/NTOPIC, k=nk%NTOPIC;
    int h=blockIdx.y, w=threadIdx.x;
    const float* base=g_dm+(long)n*2*LTOK*NTOPIC+(long)half*LTOK*NTOPIC;
    float acc=0.f;
    for(int dh=-1;dh<=1;dh++){
        int hh=h+dh; if(hh<0||hh>=64) continue;
        for(int dw=-1;dw<=1;dw++){
            int ww=w+dw; if(ww<0||ww>=64) continue;
            acc+=base[k*4096+hh*64+ww];
        }
    }
    acc*=(1.f/9.f);
    int l=h*64+w;
    out[((long)n*LTOK+l)*NTOPIC+k]=base[(long)l*NTOPIC+k]*acc;
}

// ======================= host side =======================
static void g1(const GOp& o){
    dim3 g((o.N+63)/64,(o.M+127)/128,1);
    gemm_k<<<g,256,GEMM_SMEM>>>(o,o,o);
}
static void g3(const GOp& a,const GOp& b,const GOp& c){
    int mt=(a.M+127)/128;
    int t2=(b.M+127)/128; if(t2>mt) mt=t2;
    int t3=(c.M+127)/128; if(t3>mt) mt=t3;
    int nt=(a.N+63)/64;
    int n2=(b.N+63)/64; if(n2>nt) nt=n2;
    int n3=(c.N+63)/64; if(n3>nt) nt=n3;
    dim3 g(nt,mt,3);
    gemm_k<<<g,256,GEMM_SMEM>>>(a,b,c);
}

struct Ptrs {
    float *f,*fo,*seeds,*seedsF,*nf,*q,*k,*v,*hid,*ffn,*KV,*Ksum,*dm,*sumh;
    int *cntm;
};

static void enc_layer(Ptrs& P,float* x,const float* src,int nbX,int rpbX,int nbS,int rpbS,
                      const int* cx,const int* cs,
                      const float* Wq,const float* Wk,const float* Wv,
                      const float* Wm,const float* W1,const float* W2)
{
    int Mx=nbX*rpbX, Ms=nbS*rpbS;
    float* msg=P.q;
    GOp oq{x,  nullptr,Wq,P.q, Mx,256,256,0,256,0L,rpbX,cx,1.f,1};
    GOp ok{src,nullptr,Wk,P.k, Ms,256,256,0,256,0L,rpbS,cs,1.f,1};
    GOp ov{src,nullptr,Wv,P.v, Ms,256,256,0,256,0L,rpbS,cs,1.f,0};
    g3(oq,ok,ov);
    long kvN=(long)nbS*NHEAD*1024, ksN=(long)nbS*NHEAD*32;
    zero2_k<<<(int)((kvN+255)/256),256>>>(P.KV,kvN,P.Ksum,ksN);
    dim3 gkv((rpbS+511)/512,nbS*NHEAD);
    kv_reduce_k<<<gkv,256>>>(P.k,P.v,P.KV,P.Ksum,rpbS,512,cs);
    msg_k<<<Mx,256>>>(P.q,P.KV,P.Ksum,msg,rpbX,nbS,cx);
    GOp om{msg,nullptr,Wm,P.ffn, Mx,256,256,0,256,0L,rpbX,cx,1.f,0};
    g1(om);
    ln_k<<<Mx,256>>>(P.ffn,msg,nullptr,rpbX,cx,1e-5f);
    GOp oh{x,msg,W1,P.hid, Mx,512,512,0,512,0L,rpbX,cx,1.f,2};
    g1(oh);
    GOp of{P.hid,nullptr,W2,P.ffn, Mx,256,512,0,256,0L,rpbX,cx,1.f,0};
    g1(of);
    ln_k<<<Mx,256>>>(P.ffn,nullptr,x,rpbX,cx,1e-5f);
}

extern "C" void kernel_launch(void* const* d_in, const int* in_sizes, int n_in,
                              void* d_out, int out_size)
{
    static Ptrs P; static bool inited=false;
    if(!inited){
        cudaGetSymbolAddress((void**)&P.f,g_f);
        cudaGetSymbolAddress((void**)&P.fo,g_fo);
        cudaGetSymbolAddress((void**)&P.seeds,g_seeds);
        cudaGetSymbolAddress((void**)&P.seedsF,g_seedsF);
        cudaGetSymbolAddress((void**)&P.nf,g_nf);
        cudaGetSymbolAddress((void**)&P.q,g_q);
        cudaGetSymbolAddress((void**)&P.k,g_k);
        cudaGetSymbolAddress((void**)&P.v,g_v);
        cudaGetSymbolAddress((void**)&P.hid,g_hid);
        cudaGetSymbolAddress((void**)&P.ffn,g_ffn);
        cudaGetSymbolAddress((void**)&P.KV,g_KV);
        cudaGetSymbolAddress((void**)&P.Ksum,g_Ksum);
        cudaGetSymbolAddress((void**)&P.dm,g_dm);
        cudaGetSymbolAddress((void**)&P.sumh,g_sumh);
        cudaGetSymbolAddress((void**)&P.cntm,g_cntm);
        cudaFuncSetAttribute(gemm_k,cudaFuncAttributeMaxDynamicSharedMemorySize,GEMM_SMEM);
        inited=true;
    }
    const float* in_f0=(const float*)d_in[0];
    const float* in_f1=(const float*)d_in[1];
    const float* in_t0=(const float*)d_in[2];
    const float* in_t1=(const float*)d_in[3];
    const float* in_st=(const float*)d_in[4];
    const float* Wq=(const float*)d_in[5];
    const float* Wk=(const float*)d_in[6];
    const float* Wv=(const float*)d_in[7];
    const float* Wm=(const float*)d_in[8];
    const float* W1=(const float*)d_in[9];
    const float* W2=(const float*)d_in[10];
    float* out=(float*)d_out;

    const long FREG=(long)NBATCH*LTOK*CDIM;
    const long TREG=(long)NBATCH*LTOK*NTOPIC;
    float* out_f0=out;
    float* out_f1=out+FREG;
    float* out_t0=out+2*FREG;
    float* out_t1=out+2*FREG+TREG;
    float* f0=P.f;
    float* f1=P.f+FREG;

    auto LW=[&](int i,const float*& wq,const float*& wk,const float*& wv,
                const float*& wm,const float*& w1,const float*& w2){
        wq=Wq+(long)i*256*256; wk=Wk+(long)i*256*256; wv=Wv+(long)i*256*256;
        wm=Wm+(long)i*256*256; w1=W1+(long)i*512*512; w2=W2+(long)i*512*256;
    };
    const float *wq,*wk,*wv,*wm,*w1,*w2;

    concatfeat_k<<<(int)((2*FREG+255)/256),256>>>(in_f0,in_f1);
    bcast_seeds_k<<<(NBATCH*NTOPIC*CDIM+255)/256,256>>>(in_st);
    tm_k<<<NBATCH*NTOPIC,128>>>(in_t0,in_t1);

    LW(0,wq,wk,wv,wm,w1,w2);
    enc_layer(P,P.seeds,P.fo,NBATCH,NTOPIC,NBATCH,2*LTOK,nullptr,nullptr,wq,wk,wv,wm,w1,w2);

    copy_k<<<(int)((FREG+255)/256),256>>>(f0,in_f0,FREG);
    copy_k<<<(int)((FREG+255)/256),256>>>(f1,in_f1,FREG);
    colstat_k<<<NBATCH,128>>>();
    tmidx_k<<<NBATCH*NTOPIC,32>>>();
    topic_k<<<NBATCH*NTOPIC,96>>>(in_t0,in_t1);

    LW(1,wq,wk,wv,wm,w1,w2);
    enc_layer(P,P.f,P.seeds,2*NBATCH,LTOK,NBATCH,NTOPIC,nullptr,nullptr,wq,wk,wv,wm,w1,w2);
    LW(2,wq,wk,wv,wm,w1,w2);
    enc_layer(P,P.seeds,P.fo,NBATCH,NTOPIC,NBATCH,2*LTOK,nullptr,nullptr,wq,wk,wv,wm,w1,w2);
    LW(3,wq,wk,wv,wm,w1,w2);
    enc_layer(P,P.f,P.seeds,2*NBATCH,LTOK,NBATCH,NTOPIC,nullptr,nullptr,wq,wk,wv,wm,w1,w2);

    seedfin_k<<<NBATCH*NTOPIC,256>>>();
    GOp od{P.fo,nullptr,P.seedsF,P.dm, NBATCH*2*LTOK,NTOPIC,256, 1,256,(long)NTOPIC*256, 2*LTOK,nullptr,0.0625f,0};
    g1(od);

    zero_k<<<(2*NBATCH*NTOPIC+255)/256,256>>>(P.sumh,2*NBATCH*NTOPIC);
    prob_k<<<(NBATCH*2*LTOK)/64,64>>>();
    theta_k<<<NBATCH,32>>>();
    selbuild_k<<<NSAMP*2*NBATCH,32>>>();
    cond_k<<<1,32>>>();
    repack_cnt_k<<<1,64>>>();

    zero_k<<<(int)((2*FREG+255)/256),256>>>(out_f0,2*FREG);

    float* nfA=P.nf;
    float* nfB=P.nf+(long)(NSAMP*NBATCH)*LTOK*CDIM;
    const int* cm =P.cntm;
    const int* cm0=P.cntm;
    const int* cm1=P.cntm+NSAMP*NBATCH;
    gatherM_k<<<dim3(LTOK,NBATCH,2*NSAMP),256>>>(f0,f1);
    for(int idt=0;idt<2;idt++){
        const float *aq,*ak,*av,*am,*a1,*a2,*bq,*bk,*bv,*bm,*b1,*b2;
        LW(4+idt*2,aq,ak,av,am,a1,a2);
        LW(5+idt*2,bq,bk,bv,bm,b1,b2);
        enc_layer(P,P.nf,P.nf,NBM,LTOK,NBM,LTOK,cm,cm,aq,ak,av,am,a1,a2);
        enc_layer(P,nfA,nfB,NSAMP*NBATCH,LTOK,NSAMP*NBATCH,LTOK,cm0,cm1,bq,bk,bv,bm,b1,b2);
        enc_layer(P,nfB,nfA,NSAMP*NBATCH,LTOK,NSAMP*NBATCH,LTOK,cm1,cm0,bq,bk,bv,bm,b1,b2);
    }
    scatterM_k<<<dim3(LTOK,NBATCH,2*NSAMP),256>>>(out_f0,out_f1);

    blend_k<<<NBATCH*LTOK,256>>>(out_f0,f0,0);
    blend_k<<<NBATCH*LTOK,256>>>(out_f1,f1,1);
    tmi_k<<<dim3(NBATCH*NTOPIC,64),64>>>(0,out_t0);
    tmi_k<<<dim3(NBATCH*NTOPIC,64),64>>>(1,out_t1);
}